// round 1
// baseline (speedup 1.0000x reference)
#include <cuda_runtime.h>
#include <math.h>

// ---------------- problem constants ----------------
#define Dv 512
#define Nv 16384          // B*H*W = 16*32*32
#define Kv 2048

// d_out layout (floats), tuple order:
// q[16,512,32,32], distance_prob[N,K], commitment_loss, loss, codebook_sum,
// embeddings_new[K,D], N_new[K], z_avg_new[K,D]
#define OFF_Q    0ULL
#define OFF_DP   8388608ULL
#define OFF_CL   41943040ULL
#define OFF_LOSS 41943041ULL
#define OFF_CBS  41943042ULL
#define OFF_EMB  41943043ULL
#define OFF_NNEW 42991619ULL
#define OFF_ZAVG 42993667ULL

typedef unsigned long long u64;

// ---------------- scratch (static device memory; no allocations) ----------------
__device__ float g_znormT[(size_t)Dv * Nv];   // [D][N]  33.5 MB
__device__ float g_cbnormT[(size_t)Dv * Kv];  // [D][K]   4 MB
__device__ float g_zsq[Nv];
__device__ float g_cbsq[Kv];
__device__ float g_logits[(size_t)Nv * Kv];   // [N][K] 134 MB
__device__ int   g_idx[Nv];
__device__ float g_ntotal[Kv];
__device__ float g_commit;
__device__ float g_cbsum;
__device__ float g_nsum;

// ---------------- packed fp32x2 helpers (Blackwell FFMA2) ----------------
static __device__ __forceinline__ u64 dup2f(float v) {
    u64 r;
    asm("mov.b64 %0, {%1, %1};" : "=l"(r) : "f"(v));
    return r;
}
#define FMA2(acc, a, b) asm("fma.rn.f32x2 %0, %1, %2, %0;" : "+l"(acc) : "l"(a), "l"(b))
static __device__ __forceinline__ void unpack2f(u64 v, float& lo, float& hi) {
    asm("mov.b64 {%0, %1}, %2;" : "=f"(lo), "=f"(hi) : "l"(v));
}

// ---------------- init: zero accumulators (must be fresh every replay) ----------------
__global__ void k_init() {
    int t = blockIdx.x * 256 + threadIdx.x;
    if (t < Kv) g_ntotal[t] = 0.0f;
    if (t == 0) { g_commit = 0.0f; g_cbsum = 0.0f; }
}

// ---------------- normalize codebook: [K,D] rows -> cb_norm_T [D,K], cbsq[k] ----------------
__global__ void __launch_bounds__(128) k_normalize_cb(const float* __restrict__ emb) {
    __shared__ float red[128];
    __shared__ float sinv;
    const int k = blockIdx.x;
    const int t = threadIdx.x;
    const float4 v = *((const float4*)(emb + (size_t)k * Dv) + t);
    red[t] = v.x * v.x + v.y * v.y + v.z * v.z + v.w * v.w;
    __syncthreads();
    for (int s = 64; s > 0; s >>= 1) {
        if (t < s) red[t] += red[t + s];
        __syncthreads();
    }
    if (t == 0) {
        float s = red[0];
        float iv = 1.0f / fmaxf(sqrtf(s), 1e-12f);
        sinv = iv;
        g_cbsq[k] = s * iv * iv;
    }
    __syncthreads();
    const float iv = sinv;
    const int d0 = 4 * t;
    g_cbnormT[(size_t)(d0 + 0) * Kv + k] = v.x * iv;
    g_cbnormT[(size_t)(d0 + 1) * Kv + k] = v.y * iv;
    g_cbnormT[(size_t)(d0 + 2) * Kv + k] = v.z * iv;
    g_cbnormT[(size_t)(d0 + 3) * Kv + k] = v.w * iv;
}

// ---------------- normalize z: [B,D,H,W] -> z_norm_T [D,N], zsq[n] ----------------
// block = (b,h) pair; thread = (w = t&31, dg = t>>5); fully coalesced reads & writes.
__global__ void __launch_bounds__(256) k_normalize_z(const float* __restrict__ z) {
    __shared__ float ssb[256];
    __shared__ float inv[32];
    const int bid = blockIdx.x;
    const int b = bid >> 5, h = bid & 31;
    const int t = threadIdx.x;
    const int w = t & 31, dg = t >> 5;
    const float* zp = z + (size_t)b * 524288 + h * 32 + w;  // z[b][d][h][w], d-stride 1024
    float ss = 0.0f;
#pragma unroll 8
    for (int i = 0; i < 64; i++) {
        int d = dg + (i << 3);
        float v = zp[(size_t)d * 1024];
        ss += v * v;
    }
    ssb[t] = ss;
    __syncthreads();
    if (t < 32) {
        float s = 0.0f;
#pragma unroll
        for (int g = 0; g < 8; g++) s += ssb[(g << 5) + t];
        float iv = 1.0f / fmaxf(sqrtf(s), 1e-12f);
        inv[t] = iv;
        g_zsq[(bid << 5) + t] = s * iv * iv;
    }
    __syncthreads();
    const int n0 = bid << 5;
    const float iv = inv[w];
#pragma unroll 8
    for (int i = 0; i < 64; i++) {
        int d = dg + (i << 3);
        float v = zp[(size_t)d * 1024];
        g_znormT[(size_t)d * Nv + n0 + w] = v * iv;  // consecutive w -> coalesced
    }
}

// ---------------- GEMM: logits[n][k] = zsq[n] + cbsq[k] - 2 * <z_norm[n], cb_norm[k]> ----------------
// A = z_norm_T [512][16384], B = cb_norm_T [512][2048]. 128x128x8 tile, 8x8/thread,
// accumulators packed in fp32x2 pairs along the code (j) dimension.
__global__ void __launch_bounds__(256) k_gemm() {
    __shared__ float As[2][8][128];
    __shared__ float Bs[2][8][128];
    const int t = threadIdx.x;
    const int m0 = blockIdx.y << 7;
    const int n0 = blockIdx.x << 7;
    const int lrow = t >> 5;          // k-row within tile (0..7)
    const int lcol = (t & 31) << 2;   // column within tile (step 4)
    const float* Ag = g_znormT + (size_t)lrow * Nv + m0 + lcol;
    const float* Bg = g_cbnormT + (size_t)lrow * Kv + n0 + lcol;
    const int tm = (t >> 4) << 3;
    const int tn = (t & 15) << 3;

    u64 acc[8][4];
#pragma unroll
    for (int i = 0; i < 8; i++)
#pragma unroll
        for (int j = 0; j < 4; j++) acc[i][j] = 0ULL;

    float4 a4 = *(const float4*)Ag;
    float4 b4 = *(const float4*)Bg;

#pragma unroll 1
    for (int ks = 0; ks < 64; ks++) {
        const int buf = ks & 1;
        *(float4*)&As[buf][lrow][lcol] = a4;
        *(float4*)&Bs[buf][lrow][lcol] = b4;
        __syncthreads();
        if (ks < 63) {
            a4 = *(const float4*)(Ag + (size_t)(ks + 1) * 8 * Nv);
            b4 = *(const float4*)(Bg + (size_t)(ks + 1) * 8 * Kv);
        }
#pragma unroll
        for (int kk = 0; kk < 8; kk++) {
            const ulonglong2 bq0 = *(const ulonglong2*)&Bs[buf][kk][tn];
            const ulonglong2 bq1 = *(const ulonglong2*)&Bs[buf][kk][tn + 4];
            const float4 av0 = *(const float4*)&As[buf][kk][tm];
            const float4 av1 = *(const float4*)&As[buf][kk][tm + 4];
            u64 bv[4] = {bq0.x, bq0.y, bq1.x, bq1.y};
            float av[8] = {av0.x, av0.y, av0.z, av0.w, av1.x, av1.y, av1.z, av1.w};
#pragma unroll
            for (int i = 0; i < 8; i++) {
                u64 ad = dup2f(av[i]);
#pragma unroll
                for (int j = 0; j < 4; j++) FMA2(acc[i][j], ad, bv[j]);
            }
        }
        __syncthreads();
    }

    float cbq[8];
#pragma unroll
    for (int j = 0; j < 8; j++) cbq[j] = g_cbsq[n0 + tn + j];
#pragma unroll
    for (int i = 0; i < 8; i++) {
        const float zs = g_zsq[m0 + tm + i];
        float out[8];
#pragma unroll
        for (int j = 0; j < 4; j++) {
            float lo, hi;
            unpack2f(acc[i][j], lo, hi);
            out[2 * j]     = (zs + cbq[2 * j])     - 2.0f * lo;
            out[2 * j + 1] = (zs + cbq[2 * j + 1]) - 2.0f * hi;
        }
        float* orow = g_logits + (size_t)(m0 + tm + i) * Kv + n0 + tn;
        *(float4*)orow = *(float4*)out;
        *(float4*)(orow + 4) = *(float4*)(out + 4);
    }
}

// ---------------- per-token softmax(-dist) + argmin + prob write ----------------
__global__ void __launch_bounds__(256) k_softmax(float* __restrict__ dp) {
    __shared__ float row[Kv];
    __shared__ float sv[256];
    __shared__ int si[256];
    const int n = blockIdx.x;
    const int t = threadIdx.x;
    const float* lr = g_logits + (size_t)n * Kv;
    float bv = 3.0e38f;
    int bi = 0;
#pragma unroll
    for (int j = 0; j < 8; j++) {
        int k = t + (j << 8);
        float v = lr[k];
        row[k] = v;
        if (v < bv) { bv = v; bi = k; }
    }
    sv[t] = bv; si[t] = bi;
    __syncthreads();
    for (int s = 128; s > 0; s >>= 1) {
        if (t < s) {
            float ov = sv[t + s]; int oi = si[t + s];
            if (ov < sv[t] || (ov == sv[t] && oi < si[t])) { sv[t] = ov; si[t] = oi; }
        }
        __syncthreads();
    }
    const float dmin = sv[0];
    const int kmin = si[0];
    __syncthreads();
    float ls = 0.0f;
#pragma unroll
    for (int j = 0; j < 8; j++) {
        int k = t + (j << 8);
        float e = __expf(dmin - row[k]);   // exp(x - max) with x = -dist
        row[k] = e;
        ls += e;
    }
    sv[t] = ls;
    __syncthreads();
    for (int s = 128; s > 0; s >>= 1) {
        if (t < s) sv[t] += sv[t + s];
        __syncthreads();
    }
    const float rs = 1.0f / sv[0];
    float* out = dp + (size_t)n * Kv;
#pragma unroll
    for (int j = 0; j < 8; j++) {
        int k = t + (j << 8);
        out[k] = row[k] * rs;
    }
    if (t == 0) {
        g_idx[n] = kmin;
        atomicAdd(&g_ntotal[kmin], 1.0f);
    }
}

// ---------------- z_avg_new = 0.99*z_avg (init), then += 0.01*z_norm scatter ----------------
__global__ void k_ema_init(float* __restrict__ zavg_out, const float* __restrict__ zavg_in) {
    int i = blockIdx.x * 512 + threadIdx.x;
    zavg_out[i] = 0.99f * zavg_in[i];
}

__global__ void k_scatter(float* __restrict__ zavg_out) {
    int i = blockIdx.x * 512 + threadIdx.x;   // i over [D*N), layout = z_norm_T linear
    int n = i & (Nv - 1);
    int d = i >> 14;
    float v = g_znormT[i];
    atomicAdd(zavg_out + (size_t)g_idx[n] * Dv + d, 0.01f * v);
}

// ---------------- N_new + its sum ----------------
__global__ void __launch_bounds__(1024) k_nreduce(float* __restrict__ nnew_out,
                                                  const float* __restrict__ nbuf) {
    __shared__ float red[1024];
    int t = threadIdx.x;
    float s = 0.0f;
#pragma unroll
    for (int j = 0; j < 2; j++) {
        int k = t + (j << 10);
        float v = 0.99f * nbuf[k] + 0.01f * g_ntotal[k];
        nnew_out[k] = v;
        s += v;
    }
    red[t] = s;
    __syncthreads();
    for (int st = 512; st > 0; st >>= 1) {
        if (t < st) red[t] += red[t + st];
        __syncthreads();
    }
    if (t == 0) g_nsum = red[0];
}

// ---------------- embeddings_new = z_avg_new / weights; codebook_sum ----------------
__global__ void __launch_bounds__(512) k_embnew(float* __restrict__ emb_out,
                                                const float* __restrict__ zavg_out,
                                                const float* __restrict__ nnew) {
    __shared__ float red[512];
    int i = blockIdx.x * 512 + threadIdx.x;
    int k = i >> 9;
    float nn = nnew[k];
    float nsum = g_nsum;
    float wgt = (nn + 1e-5f) / (nsum + 0.02048f) * nsum;  // (N+eps)/(n+K*eps)*n
    float e = zavg_out[i] / wgt;
    emb_out[i] = e;
    red[threadIdx.x] = fabsf(e);
    __syncthreads();
    for (int s = 256; s > 0; s >>= 1) {
        if (threadIdx.x < s) red[threadIdx.x] += red[threadIdx.x + s];
        __syncthreads();
    }
    if (threadIdx.x == 0) atomicAdd(&g_cbsum, red[0]);
}

// ---------------- q gather ([B,D,H,W]) + commitment loss accumulation ----------------
__global__ void __launch_bounds__(256) k_gather_q(float* __restrict__ q) {
    __shared__ int kidx[32];
    __shared__ float red[256];
    const int bid = blockIdx.x;
    const int b = bid >> 5, h = bid & 31;
    const int t = threadIdx.x;
    const int w = t & 31, dg = t >> 5;
    const int n0 = bid << 5;
    if (t < 32) kidx[t] = g_idx[n0 + t];
    __syncthreads();
    const int ki = kidx[w];
    float local = 0.0f;
    float* qp = q + (size_t)b * 524288 + h * 32 + w;
#pragma unroll 4
    for (int i = 0; i < 64; i++) {
        int d = dg + (i << 3);
        float e  = g_znormT[(size_t)d * Nv + ki];        // gather (L2-resident 4MB region)
        float zn = g_znormT[(size_t)d * Nv + n0 + w];    // coalesced
        float df = zn - e;
        local += df * df;
        qp[(size_t)d * 1024] = e;                        // coalesced in w
    }
    red[t] = local;
    __syncthreads();
    for (int s = 128; s > 0; s >>= 1) {
        if (t < s) red[t] += red[t + s];
        __syncthreads();
    }
    if (t == 0) atomicAdd(&g_commit, red[0]);
}

// ---------------- scalars ----------------
__global__ void k_finalize(float* __restrict__ out) {
    float c = g_commit * (1.0f / 8388608.0f);  // exact power-of-two mean
    out[OFF_CL]   = c;
    out[OFF_LOSS] = 0.25f * c;
    out[OFF_CBS]  = g_cbsum;
}

// ---------------- launch ----------------
extern "C" void kernel_launch(void* const* d_in, const int* in_sizes, int n_in,
                              void* d_out, int out_size) {
    const float* z    = (const float*)d_in[0];
    const float* emb  = (const float*)d_in[1];
    const float* nbuf = (const float*)d_in[2];
    const float* zavg = (const float*)d_in[3];
    float* out = (float*)d_out;

    float* q_out    = out + OFF_Q;
    float* dp_out   = out + OFF_DP;
    float* emb_out  = out + OFF_EMB;
    float* nnew_out = out + OFF_NNEW;
    float* zavg_out = out + OFF_ZAVG;

    k_init<<<8, 256>>>();
    k_normalize_cb<<<Kv, 128>>>(emb);
    k_normalize_z<<<512, 256>>>(z);
    k_gemm<<<dim3(16, 128), 256>>>();
    k_softmax<<<Nv, 256>>>(dp_out);
    k_ema_init<<<2048, 512>>>(zavg_out, zavg);
    k_scatter<<<16384, 512>>>(zavg_out);
    k_nreduce<<<1, 1024>>>(nnew_out, nbuf);
    k_embnew<<<2048, 512>>>(emb_out, zavg_out, nnew_out);
    k_gather_q<<<512, 256>>>(q_out);
    k_finalize<<<1, 1>>>(out);
}